// round 1
// baseline (speedup 1.0000x reference)
#include <cuda_runtime.h>
#include <cuda_bf16.h>
#include <cstdint>

// Problem constants
#define BATCH 32
#define CIN   512
#define COUT  2048
#define HEADS 8
#define DHEAD 256           // COUT/HEADS
#define NPIX  256           // H*W
#define SPARSITY 7

// Scratch (static device arrays; allocation-free per harness rules)
__device__ float g_q    [BATCH * COUT * NPIX];   // [b][h*256+d][n]
__device__ float g_k    [BATCH * COUT * NPIX];
__device__ float g_v    [BATCH * COUT * NPIX];
__device__ float g_ao   [BATCH * COUT * NPIX];   // attention output, [b][h*256+d][n]
__device__ float g_attn [BATCH * HEADS * NPIX * NPIX];   // [bh*256+n][m]
__device__ float g_sattn[BATCH * HEADS * NPIX * NPIX];   // softmaxed sparse attn

__device__ int   g_t7i[256 * SPARSITY];
__device__ float g_t7v[256 * SPARSITY];
__device__ int   g_csc_row[256 * 256];
__device__ float g_csc_val[256 * 256];
__device__ int   g_csc_cnt[256];

// ---------------------------------------------------------------------------
// 1) Sparsify: per row r (<256) of coeff[2048][2048], find top-7 |values| over
//    all 2048 columns (JAX top_k semantics: ties -> smaller index; values are
//    continuous random so ties are measure-zero anyway).
// ---------------------------------------------------------------------------
__global__ void sparsify_topk(const float* __restrict__ coeff) {
    int r = blockIdx.x;          // 0..255
    int t = threadIdx.x;         // 0..255
    __shared__ float av[2048];
    __shared__ float rv[256];
    __shared__ int   ri[256];

    const float* row = coeff + (size_t)r * 2048;
    for (int j = t; j < 2048; j += 256) av[j] = fabsf(row[j]);
    __syncthreads();

    for (int it = 0; it < SPARSITY; it++) {
        float best = -1.0f; int bi = 1 << 30;
        for (int j = t; j < 2048; j += 256) {
            float v = av[j];
            if (v > best) { best = v; bi = j; }   // strided scan: keeps smallest j on tie
        }
        rv[t] = best; ri[t] = bi;
        __syncthreads();
        for (int s = 128; s > 0; s >>= 1) {
            if (t < s) {
                if (rv[t + s] > rv[t] || (rv[t + s] == rv[t] && ri[t + s] < ri[t])) {
                    rv[t] = rv[t + s]; ri[t] = ri[t + s];
                }
            }
            __syncthreads();
        }
        if (t == 0) {
            int idx = ri[0];
            g_t7i[r * SPARSITY + it] = idx;
            g_t7v[r * SPARSITY + it] = row[idx];
            av[idx] = -2.0f;  // exclude from further iterations
        }
        __syncthreads();
    }
}

// ---------------------------------------------------------------------------
// 2) Build CSC of coeff_s[:256,:256] deterministically (fixed row order).
//    Column p gathers (row m, value) for every selected entry with col==p.
// ---------------------------------------------------------------------------
__global__ void build_csc() {
    int p = threadIdx.x;   // 0..255 (single block)
    int cnt = 0;
    for (int r = 0; r < 256; r++) {
        #pragma unroll
        for (int j = 0; j < SPARSITY; j++) {
            if (g_t7i[r * SPARSITY + j] == p) {
                g_csc_row[p * 256 + cnt] = r;
                g_csc_val[p * 256 + cnt] = g_t7v[r * SPARSITY + j];
                cnt++;
            }
        }
    }
    g_csc_cnt[p] = cnt;
}

// ---------------------------------------------------------------------------
// GEMM tile scheme shared by all kernels: 128x128 C-tile, BK=8, 256 threads,
// 8x8 microtile per thread, float4 smem fragment loads.
// rows[i] = ty*4 + (i&3) + (i>=4)*64 ;  cols[j] = tx*4 + (j&3) + (j>=4)*64
// ---------------------------------------------------------------------------

// 3) conv1x1 GEMM:  Y[b][o][n] = sum_c W[o][c] * X[b][c][n] + bias[o]
//    grid = (NPIX/128, COUT/128, BATCH)
__global__ __launch_bounds__(256) void conv_gemm(
    const float* __restrict__ W, const float* __restrict__ bias,
    const float* __restrict__ X, float* __restrict__ Y, int K)
{
    __shared__ float As[8][128];
    __shared__ float Bs[8][128];

    int b  = blockIdx.z;
    int m0 = blockIdx.y * 128;
    int n0 = blockIdx.x * 128;
    const float* Xb = X + (size_t)b * K * NPIX;
    float*       Yb = Y + (size_t)b * COUT * NPIX;

    int t  = threadIdx.x;
    int tx = t & 15, ty = t >> 4;
    int lr = t >> 1, lk = (t & 1) * 4;    // A: 128 rows x 8 k (transpose-scatter)
    int bk = t >> 5, bc = (t & 31) * 4;   // B: 8 k x 128 cols (direct float4)

    float acc[8][8];
    #pragma unroll
    for (int i = 0; i < 8; i++)
        #pragma unroll
        for (int j = 0; j < 8; j++) acc[i][j] = 0.0f;

    for (int k0 = 0; k0 < K; k0 += 8) {
        float4 a4 = *(const float4*)(W + (size_t)(m0 + lr) * K + k0 + lk);
        As[lk + 0][lr] = a4.x; As[lk + 1][lr] = a4.y;
        As[lk + 2][lr] = a4.z; As[lk + 3][lr] = a4.w;
        *(float4*)&Bs[bk][bc] =
            *(const float4*)(Xb + (size_t)(k0 + bk) * NPIX + n0 + bc);
        __syncthreads();

        #pragma unroll
        for (int kk = 0; kk < 8; kk++) {
            float a[8], bb[8];
            *(float4*)(a)      = *(float4*)&As[kk][ty * 4];
            *(float4*)(a + 4)  = *(float4*)&As[kk][ty * 4 + 64];
            *(float4*)(bb)     = *(float4*)&Bs[kk][tx * 4];
            *(float4*)(bb + 4) = *(float4*)&Bs[kk][tx * 4 + 64];
            #pragma unroll
            for (int i = 0; i < 8; i++)
                #pragma unroll
                for (int j = 0; j < 8; j++)
                    acc[i][j] += a[i] * bb[j];
        }
        __syncthreads();
    }

    #pragma unroll
    for (int i = 0; i < 8; i++) {
        int row = m0 + ty * 4 + (i & 3) + (i >> 2) * 64;
        float bv = bias[row];
        #pragma unroll
        for (int jh = 0; jh < 2; jh++) {
            float4 o;
            o.x = acc[i][jh * 4 + 0] + bv;
            o.y = acc[i][jh * 4 + 1] + bv;
            o.z = acc[i][jh * 4 + 2] + bv;
            o.w = acc[i][jh * 4 + 3] + bv;
            *(float4*)(Yb + (size_t)row * NPIX + n0 + tx * 4 + jh * 64) = o;
        }
    }
}

// 4) attn[b][h][n][m] = (sum_d q[d][n] * k[d][m]) / scale
//    grid = (2, 2, BATCH*HEADS);  A = q^T, B = k, both direct float4 loads.
__global__ __launch_bounds__(256) void attn_gemm(const float* __restrict__ scale)
{
    __shared__ float As[8][128];
    __shared__ float Bs[8][128];

    int bh = blockIdx.z;
    const float* q   = g_q    + (size_t)bh * 65536;
    const float* kp  = g_k    + (size_t)bh * 65536;
    float*       out = g_attn + (size_t)bh * 65536;

    int n0 = blockIdx.y * 128;   // output rows (n)
    int m0 = blockIdx.x * 128;   // output cols (m)

    int t  = threadIdx.x;
    int tx = t & 15, ty = t >> 4;
    int lk = t >> 5, lc = (t & 31) * 4;

    float inv = 1.0f / __ldg(scale);

    float acc[8][8];
    #pragma unroll
    for (int i = 0; i < 8; i++)
        #pragma unroll
        for (int j = 0; j < 8; j++) acc[i][j] = 0.0f;

    for (int k0 = 0; k0 < 256; k0 += 8) {
        *(float4*)&As[lk][lc] = *(const float4*)(q  + (size_t)(k0 + lk) * 256 + n0 + lc);
        *(float4*)&Bs[lk][lc] = *(const float4*)(kp + (size_t)(k0 + lk) * 256 + m0 + lc);
        __syncthreads();
        #pragma unroll
        for (int kk = 0; kk < 8; kk++) {
            float a[8], bb[8];
            *(float4*)(a)      = *(float4*)&As[kk][ty * 4];
            *(float4*)(a + 4)  = *(float4*)&As[kk][ty * 4 + 64];
            *(float4*)(bb)     = *(float4*)&Bs[kk][tx * 4];
            *(float4*)(bb + 4) = *(float4*)&Bs[kk][tx * 4 + 64];
            #pragma unroll
            for (int i = 0; i < 8; i++)
                #pragma unroll
                for (int j = 0; j < 8; j++)
                    acc[i][j] += a[i] * bb[j];
        }
        __syncthreads();
    }

    #pragma unroll
    for (int i = 0; i < 8; i++) {
        int row = n0 + ty * 4 + (i & 3) + (i >> 2) * 64;
        #pragma unroll
        for (int jh = 0; jh < 2; jh++) {
            float4 o;
            o.x = acc[i][jh * 4 + 0] * inv;
            o.y = acc[i][jh * 4 + 1] * inv;
            o.z = acc[i][jh * 4 + 2] * inv;
            o.w = acc[i][jh * 4 + 3] * inv;
            *(float4*)(out + (size_t)row * 256 + m0 + tx * 4 + jh * 64) = o;
        }
    }
}

// 5) Sparse mix + softmax. One block per attn row (bh*256+n), 128 threads.
//    sp[p] = sum_{(m,v) in CSC col p} arow[m]*v ;  then softmax over p.
__global__ __launch_bounds__(128) void mix_softmax()
{
    int row = blockIdx.x;        // 0..65535
    int t   = threadIdx.x;       // 0..127
    __shared__ float arow[256];
    __shared__ float sp[256];
    __shared__ float red[128];

    const float* src = g_attn + (size_t)row * 256;
    arow[t]       = src[t];
    arow[t + 128] = src[t + 128];
    __syncthreads();

    #pragma unroll
    for (int pp = 0; pp < 2; pp++) {
        int p = t + pp * 128;
        int c = g_csc_cnt[p];
        const int*   ri = g_csc_row + p * 256;
        const float* rv = g_csc_val + p * 256;
        float s = 0.0f;
        for (int j = 0; j < c; j++) s += arow[ri[j]] * rv[j];
        sp[p] = s;
    }
    __syncthreads();

    red[t] = fmaxf(sp[t], sp[t + 128]);
    __syncthreads();
    for (int s = 64; s > 0; s >>= 1) {
        if (t < s) red[t] = fmaxf(red[t], red[t + s]);
        __syncthreads();
    }
    float mx = red[0];
    __syncthreads();

    float e0 = __expf(sp[t] - mx);
    float e1 = __expf(sp[t + 128] - mx);
    red[t] = e0 + e1;
    __syncthreads();
    for (int s = 64; s > 0; s >>= 1) {
        if (t < s) red[t] += red[t + s];
        __syncthreads();
    }
    float inv = 1.0f / red[0];

    float* dst = g_sattn + (size_t)row * 256;
    dst[t]       = e0 * inv;
    dst[t + 128] = e1 * inv;
}

// 6) ao[b][h*256+d][n] = sum_m v[d][m] * sattn[n][m]
//    grid = (2, 2, BATCH*HEADS);  A = v (transpose-scatter), B = sattn^T.
__global__ __launch_bounds__(256) void av_gemm()
{
    __shared__ float As[8][128];
    __shared__ float Bs[8][128];

    int bh = blockIdx.z;
    const float* v  = g_v     + (size_t)bh * 65536;
    const float* sa = g_sattn + (size_t)bh * 65536;
    float*       ao = g_ao    + (size_t)bh * 65536;

    int d0 = blockIdx.y * 128;   // output rows (d)
    int n0 = blockIdx.x * 128;   // output cols (n)

    int t  = threadIdx.x;
    int tx = t & 15, ty = t >> 4;
    int lr = t >> 1, lk = (t & 1) * 4;

    float acc[8][8];
    #pragma unroll
    for (int i = 0; i < 8; i++)
        #pragma unroll
        for (int j = 0; j < 8; j++) acc[i][j] = 0.0f;

    for (int k0 = 0; k0 < 256; k0 += 8) {
        float4 a4 = *(const float4*)(v  + (size_t)(d0 + lr) * 256 + k0 + lk);
        As[lk + 0][lr] = a4.x; As[lk + 1][lr] = a4.y;
        As[lk + 2][lr] = a4.z; As[lk + 3][lr] = a4.w;
        float4 b4 = *(const float4*)(sa + (size_t)(n0 + lr) * 256 + k0 + lk);
        Bs[lk + 0][lr] = b4.x; Bs[lk + 1][lr] = b4.y;
        Bs[lk + 2][lr] = b4.z; Bs[lk + 3][lr] = b4.w;
        __syncthreads();
        #pragma unroll
        for (int kk = 0; kk < 8; kk++) {
            float a[8], bb[8];
            *(float4*)(a)      = *(float4*)&As[kk][ty * 4];
            *(float4*)(a + 4)  = *(float4*)&As[kk][ty * 4 + 64];
            *(float4*)(bb)     = *(float4*)&Bs[kk][tx * 4];
            *(float4*)(bb + 4) = *(float4*)&Bs[kk][tx * 4 + 64];
            #pragma unroll
            for (int i = 0; i < 8; i++)
                #pragma unroll
                for (int j = 0; j < 8; j++)
                    acc[i][j] += a[i] * bb[j];
        }
        __syncthreads();
    }

    #pragma unroll
    for (int i = 0; i < 8; i++) {
        int row = d0 + ty * 4 + (i & 3) + (i >> 2) * 64;
        #pragma unroll
        for (int jh = 0; jh < 2; jh++) {
            float4 o;
            o.x = acc[i][jh * 4 + 0];
            o.y = acc[i][jh * 4 + 1];
            o.z = acc[i][jh * 4 + 2];
            o.w = acc[i][jh * 4 + 3];
            *(float4*)(ao + (size_t)row * 256 + n0 + tx * 4 + jh * 64) = o;
        }
    }
}

// ---------------------------------------------------------------------------
extern "C" void kernel_launch(void* const* d_in, const int* in_sizes, int n_in,
                              void* d_out, int out_size)
{
    const float* x     = (const float*)d_in[0];
    const float* Wq    = (const float*)d_in[1];
    const float* bq    = (const float*)d_in[2];
    const float* Wk    = (const float*)d_in[3];
    const float* bk    = (const float*)d_in[4];
    const float* Wv    = (const float*)d_in[5];
    const float* bv    = (const float*)d_in[6];
    const float* Wo    = (const float*)d_in[7];
    const float* bo    = (const float*)d_in[8];
    const float* coeff = (const float*)d_in[9];
    const float* scale = (const float*)d_in[10];
    float* out = (float*)d_out;

    float *pq, *pk, *pv, *pao;
    cudaGetSymbolAddress((void**)&pq,  g_q);
    cudaGetSymbolAddress((void**)&pk,  g_k);
    cudaGetSymbolAddress((void**)&pv,  g_v);
    cudaGetSymbolAddress((void**)&pao, g_ao);

    sparsify_topk<<<256, 256>>>(coeff);
    build_csc<<<1, 256>>>();

    dim3 gconv(NPIX / 128, COUT / 128, BATCH);          // (2,16,32)
    conv_gemm<<<gconv, 256>>>(Wq, bq, x, pq, CIN);
    conv_gemm<<<gconv, 256>>>(Wk, bk, x, pk, CIN);
    conv_gemm<<<gconv, 256>>>(Wv, bv, x, pv, CIN);

    attn_gemm<<<dim3(2, 2, BATCH * HEADS), 256>>>(scale);
    mix_softmax<<<BATCH * HEADS * NPIX, 128>>>();
    av_gemm<<<dim3(2, 2, BATCH * HEADS), 256>>>();

    conv_gemm<<<gconv, 256>>>(Wo, bo, pao, out, COUT);
}

// round 2
// speedup vs baseline: 1.0019x; 1.0019x over previous
#include <cuda_runtime.h>
#include <cuda_bf16.h>
#include <cstdint>

// Problem constants
#define BATCH 32
#define CIN   512
#define COUT  2048
#define HEADS 8
#define DHEAD 256           // COUT/HEADS
#define NPIX  256           // H*W
#define SPARSITY 7

// Scratch (static device arrays; allocation-free per harness rules)
__device__ float g_q    [BATCH * COUT * NPIX];   // [b][h*256+d][n]
__device__ float g_k    [BATCH * COUT * NPIX];
__device__ float g_v    [BATCH * COUT * NPIX];
__device__ float g_ao   [BATCH * COUT * NPIX];   // attention output, [b][h*256+d][n]
__device__ float g_attn [BATCH * HEADS * NPIX * NPIX];   // [bh*256+n][m]
__device__ float g_sattn[BATCH * HEADS * NPIX * NPIX];   // softmaxed sparse attn

__device__ int   g_t7i[256 * SPARSITY];
__device__ float g_t7v[256 * SPARSITY];
__device__ int   g_csc_row[256 * 256];
__device__ float g_csc_val[256 * 256];
__device__ int   g_csc_cnt[256];

// ---------------------------------------------------------------------------
// 1) Sparsify: per row r (<256) of coeff[2048][2048], find top-7 |values| over
//    all 2048 columns (JAX top_k semantics: ties -> smaller index; values are
//    continuous random so ties are measure-zero anyway).
// ---------------------------------------------------------------------------
__global__ void sparsify_topk(const float* __restrict__ coeff) {
    int r = blockIdx.x;          // 0..255
    int t = threadIdx.x;         // 0..255
    __shared__ float av[2048];
    __shared__ float rv[256];
    __shared__ int   ri[256];

    const float* row = coeff + (size_t)r * 2048;
    for (int j = t; j < 2048; j += 256) av[j] = fabsf(row[j]);
    __syncthreads();

    for (int it = 0; it < SPARSITY; it++) {
        float best = -1.0f; int bi = 1 << 30;
        for (int j = t; j < 2048; j += 256) {
            float v = av[j];
            if (v > best) { best = v; bi = j; }   // strided scan: keeps smallest j on tie
        }
        rv[t] = best; ri[t] = bi;
        __syncthreads();
        for (int s = 128; s > 0; s >>= 1) {
            if (t < s) {
                if (rv[t + s] > rv[t] || (rv[t + s] == rv[t] && ri[t + s] < ri[t])) {
                    rv[t] = rv[t + s]; ri[t] = ri[t + s];
                }
            }
            __syncthreads();
        }
        if (t == 0) {
            int idx = ri[0];
            g_t7i[r * SPARSITY + it] = idx;
            g_t7v[r * SPARSITY + it] = row[idx];
            av[idx] = -2.0f;  // exclude from further iterations
        }
        __syncthreads();
    }
}

// ---------------------------------------------------------------------------
// 2) Build CSC of coeff_s[:256,:256] deterministically (fixed row order).
//    Column p gathers (row m, value) for every selected entry with col==p.
// ---------------------------------------------------------------------------
__global__ void build_csc() {
    int p = threadIdx.x;   // 0..255 (single block)
    int cnt = 0;
    for (int r = 0; r < 256; r++) {
        #pragma unroll
        for (int j = 0; j < SPARSITY; j++) {
            if (g_t7i[r * SPARSITY + j] == p) {
                g_csc_row[p * 256 + cnt] = r;
                g_csc_val[p * 256 + cnt] = g_t7v[r * SPARSITY + j];
                cnt++;
            }
        }
    }
    g_csc_cnt[p] = cnt;
}

// ---------------------------------------------------------------------------
// GEMM tile scheme shared by all kernels: 128x128 C-tile, BK=8, 256 threads,
// 8x8 microtile per thread, float4 smem fragment loads.
// rows[i] = ty*4 + (i&3) + (i>=4)*64 ;  cols[j] = tx*4 + (j&3) + (j>=4)*64
// ---------------------------------------------------------------------------

// 3) conv1x1 GEMM:  Y[b][o][n] = sum_c W[o][c] * X[b][c][n] + bias[o]
//    grid = (NPIX/128, COUT/128, BATCH)
__global__ __launch_bounds__(256) void conv_gemm(
    const float* __restrict__ W, const float* __restrict__ bias,
    const float* __restrict__ X, float* __restrict__ Y, int K)
{
    __shared__ float As[8][128];
    __shared__ float Bs[8][128];

    int b  = blockIdx.z;
    int m0 = blockIdx.y * 128;
    int n0 = blockIdx.x * 128;
    const float* Xb = X + (size_t)b * K * NPIX;
    float*       Yb = Y + (size_t)b * COUT * NPIX;

    int t  = threadIdx.x;
    int tx = t & 15, ty = t >> 4;
    int lr = t >> 1, lk = (t & 1) * 4;    // A: 128 rows x 8 k (transpose-scatter)
    int bk = t >> 5, bc = (t & 31) * 4;   // B: 8 k x 128 cols (direct float4)

    float acc[8][8];
    #pragma unroll
    for (int i = 0; i < 8; i++)
        #pragma unroll
        for (int j = 0; j < 8; j++) acc[i][j] = 0.0f;

    for (int k0 = 0; k0 < K; k0 += 8) {
        float4 a4 = *(const float4*)(W + (size_t)(m0 + lr) * K + k0 + lk);
        As[lk + 0][lr] = a4.x; As[lk + 1][lr] = a4.y;
        As[lk + 2][lr] = a4.z; As[lk + 3][lr] = a4.w;
        *(float4*)&Bs[bk][bc] =
            *(const float4*)(Xb + (size_t)(k0 + bk) * NPIX + n0 + bc);
        __syncthreads();

        #pragma unroll
        for (int kk = 0; kk < 8; kk++) {
            float a[8], bb[8];
            *(float4*)(a)      = *(float4*)&As[kk][ty * 4];
            *(float4*)(a + 4)  = *(float4*)&As[kk][ty * 4 + 64];
            *(float4*)(bb)     = *(float4*)&Bs[kk][tx * 4];
            *(float4*)(bb + 4) = *(float4*)&Bs[kk][tx * 4 + 64];
            #pragma unroll
            for (int i = 0; i < 8; i++)
                #pragma unroll
                for (int j = 0; j < 8; j++)
                    acc[i][j] += a[i] * bb[j];
        }
        __syncthreads();
    }

    #pragma unroll
    for (int i = 0; i < 8; i++) {
        int row = m0 + ty * 4 + (i & 3) + (i >> 2) * 64;
        float bv = bias[row];
        #pragma unroll
        for (int jh = 0; jh < 2; jh++) {
            float4 o;
            o.x = acc[i][jh * 4 + 0] + bv;
            o.y = acc[i][jh * 4 + 1] + bv;
            o.z = acc[i][jh * 4 + 2] + bv;
            o.w = acc[i][jh * 4 + 3] + bv;
            *(float4*)(Yb + (size_t)row * NPIX + n0 + tx * 4 + jh * 64) = o;
        }
    }
}

// 4) attn[b][h][n][m] = (sum_d q[d][n] * k[d][m]) / scale
//    grid = (2, 2, BATCH*HEADS);  A = q^T, B = k, both direct float4 loads.
__global__ __launch_bounds__(256) void attn_gemm(const float* __restrict__ scale)
{
    __shared__ float As[8][128];
    __shared__ float Bs[8][128];

    int bh = blockIdx.z;
    const float* q   = g_q    + (size_t)bh * 65536;
    const float* kp  = g_k    + (size_t)bh * 65536;
    float*       out = g_attn + (size_t)bh * 65536;

    int n0 = blockIdx.y * 128;   // output rows (n)
    int m0 = blockIdx.x * 128;   // output cols (m)

    int t  = threadIdx.x;
    int tx = t & 15, ty = t >> 4;
    int lk = t >> 5, lc = (t & 31) * 4;

    float inv = 1.0f / __ldg(scale);

    float acc[8][8];
    #pragma unroll
    for (int i = 0; i < 8; i++)
        #pragma unroll
        for (int j = 0; j < 8; j++) acc[i][j] = 0.0f;

    for (int k0 = 0; k0 < 256; k0 += 8) {
        *(float4*)&As[lk][lc] = *(const float4*)(q  + (size_t)(k0 + lk) * 256 + n0 + lc);
        *(float4*)&Bs[lk][lc] = *(const float4*)(kp + (size_t)(k0 + lk) * 256 + m0 + lc);
        __syncthreads();
        #pragma unroll
        for (int kk = 0; kk < 8; kk++) {
            float a[8], bb[8];
            *(float4*)(a)      = *(float4*)&As[kk][ty * 4];
            *(float4*)(a + 4)  = *(float4*)&As[kk][ty * 4 + 64];
            *(float4*)(bb)     = *(float4*)&Bs[kk][tx * 4];
            *(float4*)(bb + 4) = *(float4*)&Bs[kk][tx * 4 + 64];
            #pragma unroll
            for (int i = 0; i < 8; i++)
                #pragma unroll
                for (int j = 0; j < 8; j++)
                    acc[i][j] += a[i] * bb[j];
        }
        __syncthreads();
    }

    #pragma unroll
    for (int i = 0; i < 8; i++) {
        int row = n0 + ty * 4 + (i & 3) + (i >> 2) * 64;
        #pragma unroll
        for (int jh = 0; jh < 2; jh++) {
            float4 o;
            o.x = acc[i][jh * 4 + 0] * inv;
            o.y = acc[i][jh * 4 + 1] * inv;
            o.z = acc[i][jh * 4 + 2] * inv;
            o.w = acc[i][jh * 4 + 3] * inv;
            *(float4*)(out + (size_t)row * 256 + m0 + tx * 4 + jh * 64) = o;
        }
    }
}

// 5) Sparse mix + softmax. One block per attn row (bh*256+n), 128 threads.
//    sp[p] = sum_{(m,v) in CSC col p} arow[m]*v ;  then softmax over p.
__global__ __launch_bounds__(128) void mix_softmax()
{
    int row = blockIdx.x;        // 0..65535
    int t   = threadIdx.x;       // 0..127
    __shared__ float arow[256];
    __shared__ float sp[256];
    __shared__ float red[128];

    const float* src = g_attn + (size_t)row * 256;
    arow[t]       = src[t];
    arow[t + 128] = src[t + 128];
    __syncthreads();

    #pragma unroll
    for (int pp = 0; pp < 2; pp++) {
        int p = t + pp * 128;
        int c = g_csc_cnt[p];
        const int*   ri = g_csc_row + p * 256;
        const float* rv = g_csc_val + p * 256;
        float s = 0.0f;
        for (int j = 0; j < c; j++) s += arow[ri[j]] * rv[j];
        sp[p] = s;
    }
    __syncthreads();

    red[t] = fmaxf(sp[t], sp[t + 128]);
    __syncthreads();
    for (int s = 64; s > 0; s >>= 1) {
        if (t < s) red[t] = fmaxf(red[t], red[t + s]);
        __syncthreads();
    }
    float mx = red[0];
    __syncthreads();

    float e0 = __expf(sp[t] - mx);
    float e1 = __expf(sp[t + 128] - mx);
    red[t] = e0 + e1;
    __syncthreads();
    for (int s = 64; s > 0; s >>= 1) {
        if (t < s) red[t] += red[t + s];
        __syncthreads();
    }
    float inv = 1.0f / red[0];

    float* dst = g_sattn + (size_t)row * 256;
    dst[t]       = e0 * inv;
    dst[t + 128] = e1 * inv;
}

// 6) ao[b][h*256+d][n] = sum_m v[d][m] * sattn[n][m]
//    grid = (2, 2, BATCH*HEADS);  A = v (transpose-scatter), B = sattn^T.
__global__ __launch_bounds__(256) void av_gemm()
{
    __shared__ float As[8][128];
    __shared__ float Bs[8][128];

    int bh = blockIdx.z;
    const float* v  = g_v     + (size_t)bh * 65536;
    const float* sa = g_sattn + (size_t)bh * 65536;
    float*       ao = g_ao    + (size_t)bh * 65536;

    int d0 = blockIdx.y * 128;   // output rows (d)
    int n0 = blockIdx.x * 128;   // output cols (n)

    int t  = threadIdx.x;
    int tx = t & 15, ty = t >> 4;
    int lr = t >> 1, lk = (t & 1) * 4;

    float acc[8][8];
    #pragma unroll
    for (int i = 0; i < 8; i++)
        #pragma unroll
        for (int j = 0; j < 8; j++) acc[i][j] = 0.0f;

    for (int k0 = 0; k0 < 256; k0 += 8) {
        float4 a4 = *(const float4*)(v  + (size_t)(d0 + lr) * 256 + k0 + lk);
        As[lk + 0][lr] = a4.x; As[lk + 1][lr] = a4.y;
        As[lk + 2][lr] = a4.z; As[lk + 3][lr] = a4.w;
        float4 b4 = *(const float4*)(sa + (size_t)(n0 + lr) * 256 + k0 + lk);
        Bs[lk + 0][lr] = b4.x; Bs[lk + 1][lr] = b4.y;
        Bs[lk + 2][lr] = b4.z; Bs[lk + 3][lr] = b4.w;
        __syncthreads();
        #pragma unroll
        for (int kk = 0; kk < 8; kk++) {
            float a[8], bb[8];
            *(float4*)(a)      = *(float4*)&As[kk][ty * 4];
            *(float4*)(a + 4)  = *(float4*)&As[kk][ty * 4 + 64];
            *(float4*)(bb)     = *(float4*)&Bs[kk][tx * 4];
            *(float4*)(bb + 4) = *(float4*)&Bs[kk][tx * 4 + 64];
            #pragma unroll
            for (int i = 0; i < 8; i++)
                #pragma unroll
                for (int j = 0; j < 8; j++)
                    acc[i][j] += a[i] * bb[j];
        }
        __syncthreads();
    }

    #pragma unroll
    for (int i = 0; i < 8; i++) {
        int row = d0 + ty * 4 + (i & 3) + (i >> 2) * 64;
        #pragma unroll
        for (int jh = 0; jh < 2; jh++) {
            float4 o;
            o.x = acc[i][jh * 4 + 0];
            o.y = acc[i][jh * 4 + 1];
            o.z = acc[i][jh * 4 + 2];
            o.w = acc[i][jh * 4 + 3];
            *(float4*)(ao + (size_t)row * 256 + n0 + tx * 4 + jh * 64) = o;
        }
    }
}

// ---------------------------------------------------------------------------
extern "C" void kernel_launch(void* const* d_in, const int* in_sizes, int n_in,
                              void* d_out, int out_size)
{
    const float* x     = (const float*)d_in[0];
    const float* Wq    = (const float*)d_in[1];
    const float* bq    = (const float*)d_in[2];
    const float* Wk    = (const float*)d_in[3];
    const float* bk    = (const float*)d_in[4];
    const float* Wv    = (const float*)d_in[5];
    const float* bv    = (const float*)d_in[6];
    const float* Wo    = (const float*)d_in[7];
    const float* bo    = (const float*)d_in[8];
    const float* coeff = (const float*)d_in[9];
    const float* scale = (const float*)d_in[10];
    float* out = (float*)d_out;

    float *pq, *pk, *pv, *pao;
    cudaGetSymbolAddress((void**)&pq,  g_q);
    cudaGetSymbolAddress((void**)&pk,  g_k);
    cudaGetSymbolAddress((void**)&pv,  g_v);
    cudaGetSymbolAddress((void**)&pao, g_ao);

    sparsify_topk<<<256, 256>>>(coeff);
    build_csc<<<1, 256>>>();

    dim3 gconv(NPIX / 128, COUT / 128, BATCH);          // (2,16,32)
    conv_gemm<<<gconv, 256>>>(Wq, bq, x, pq, CIN);
    conv_gemm<<<gconv, 256>>>(Wk, bk, x, pk, CIN);
    conv_gemm<<<gconv, 256>>>(Wv, bv, x, pv, CIN);

    attn_gemm<<<dim3(2, 2, BATCH * HEADS), 256>>>(scale);
    mix_softmax<<<BATCH * HEADS * NPIX, 128>>>();
    av_gemm<<<dim3(2, 2, BATCH * HEADS), 256>>>();

    conv_gemm<<<gconv, 256>>>(Wo, bo, pao, out, COUT);
}

// round 3
// speedup vs baseline: 1.9823x; 1.9784x over previous
#include <cuda_runtime.h>
#include <cuda_bf16.h>
#include <cstdint>

#define BATCH 32
#define CIN   512
#define COUT  2048
#define HEADS 8
#define DHEAD 256
#define NPIX  256
#define SPARSITY 7

// Scratch
__device__ float g_q    [BATCH * COUT * NPIX];
__device__ float g_k    [BATCH * COUT * NPIX];
__device__ float g_v    [BATCH * COUT * NPIX];
__device__ float g_ao   [BATCH * COUT * NPIX];
__device__ float g_attn [BATCH * HEADS * NPIX * NPIX];
__device__ float g_sattn[BATCH * HEADS * NPIX * NPIX];

__device__ int   g_t7i[256 * SPARSITY];
__device__ float g_t7v[256 * SPARSITY];
__device__ int   g_csc_row[256 * 256];
__device__ float g_csc_val[256 * 256];
__device__ int   g_csc_cnt[256];

// ---------------------------------------------------------------------------
__device__ __forceinline__ unsigned f2tf(float x) {
    unsigned r;
    asm("cvt.rna.tf32.f32 %0, %1;" : "=r"(r) : "f"(x));
    return r;
}

__device__ __forceinline__ void mma_tf32(float c[4],
    unsigned a0, unsigned a1, unsigned a2, unsigned a3,
    unsigned b0, unsigned b1)
{
    asm volatile(
        "mma.sync.aligned.m16n8k8.row.col.f32.tf32.tf32.f32 "
        "{%0,%1,%2,%3}, {%4,%5,%6,%7}, {%8,%9}, {%0,%1,%2,%3};"
        : "+f"(c[0]), "+f"(c[1]), "+f"(c[2]), "+f"(c[3])
        : "r"(a0), "r"(a1), "r"(a2), "r"(a3), "r"(b0), "r"(b1));
}

// ---------------------------------------------------------------------------
// 1) top-7 |coeff| per row (rows 0..255 only matter)
// ---------------------------------------------------------------------------
__global__ void sparsify_topk(const float* __restrict__ coeff) {
    int r = blockIdx.x;
    int t = threadIdx.x;
    __shared__ float av[2048];
    __shared__ float rv[256];
    __shared__ int   ri[256];

    const float* row = coeff + (size_t)r * 2048;
    for (int j = t; j < 2048; j += 256) av[j] = fabsf(row[j]);
    __syncthreads();

    for (int it = 0; it < SPARSITY; it++) {
        float best = -1.0f; int bi = 1 << 30;
        for (int j = t; j < 2048; j += 256) {
            float v = av[j];
            if (v > best) { best = v; bi = j; }
        }
        rv[t] = best; ri[t] = bi;
        __syncthreads();
        for (int s = 128; s > 0; s >>= 1) {
            if (t < s) {
                if (rv[t + s] > rv[t] || (rv[t + s] == rv[t] && ri[t + s] < ri[t])) {
                    rv[t] = rv[t + s]; ri[t] = ri[t + s];
                }
            }
            __syncthreads();
        }
        if (t == 0) {
            int idx = ri[0];
            g_t7i[r * SPARSITY + it] = idx;
            g_t7v[r * SPARSITY + it] = row[idx];
            av[idx] = -2.0f;
        }
        __syncthreads();
    }
}

// ---------------------------------------------------------------------------
// 2) CSC of coeff_s[:256,:256]
// ---------------------------------------------------------------------------
__global__ void build_csc() {
    int p = threadIdx.x;
    int cnt = 0;
    for (int r = 0; r < 256; r++) {
        #pragma unroll
        for (int j = 0; j < SPARSITY; j++) {
            if (g_t7i[r * SPARSITY + j] == p) {
                g_csc_row[p * 256 + cnt] = r;
                g_csc_val[p * 256 + cnt] = g_t7v[r * SPARSITY + j];
                cnt++;
            }
        }
    }
    g_csc_cnt[p] = cnt;
}

// ---------------------------------------------------------------------------
// TF32 tensor-core GEMM tiles: BM=BN=128, BK=16, 256 threads (8 warps: 2m x 4n).
// Warp tile 64x32: 4 m-frags (16) x 4 n-frags (8). mma m16n8k8.
// Smem [16][136] (unsigned tf32 bits), conflict-free fragment loads.
// ---------------------------------------------------------------------------

// 3) conv1x1: Y[b][o][n] = sum_c W[o][c]*X[b][c][n] + bias[o]
//    grid (2, 16, 32)
__global__ __launch_bounds__(256) void conv_mma(
    const float* __restrict__ W, const float* __restrict__ bias,
    const float* __restrict__ X, float* __restrict__ Y, int K)
{
    __shared__ unsigned As[16][136];   // [k][m]
    __shared__ unsigned Bs[16][136];   // [k][n]

    const int b  = blockIdx.z;
    const int m0 = blockIdx.y * 128;
    const int n0 = blockIdx.x * 128;
    const float* Xb = X + (size_t)b * K * NPIX;
    float*       Yb = Y + (size_t)b * COUT * NPIX;

    const int t = threadIdx.x, lane = t & 31, wid = t >> 5;
    const int g = lane >> 2, tig = lane & 3;
    const int wm = (wid >> 2) * 64, wn = (wid & 3) * 32;
    const int lr = t >> 1,  lk = (t & 1) * 8;    // A load: row lr, 8 k's
    const int bk = t >> 4,  bc = (t & 15) * 8;   // B load: k-row bk, 8 n's

    float pa[8], pb[8];
    {   // prefetch tile 0
        const float* wp = W + (size_t)(m0 + lr) * K + lk;
        float4 a0 = *(const float4*)wp;
        float4 a1 = *(const float4*)(wp + 4);
        pa[0]=a0.x; pa[1]=a0.y; pa[2]=a0.z; pa[3]=a0.w;
        pa[4]=a1.x; pa[5]=a1.y; pa[6]=a1.z; pa[7]=a1.w;
        const float* xp = Xb + (size_t)bk * NPIX + n0 + bc;
        float4 b0 = *(const float4*)xp;
        float4 b1 = *(const float4*)(xp + 4);
        pb[0]=b0.x; pb[1]=b0.y; pb[2]=b0.z; pb[3]=b0.w;
        pb[4]=b1.x; pb[5]=b1.y; pb[6]=b1.z; pb[7]=b1.w;
    }

    float acc[4][4][4];
    #pragma unroll
    for (int i = 0; i < 4; i++)
        #pragma unroll
        for (int j = 0; j < 4; j++)
            #pragma unroll
            for (int q = 0; q < 4; q++) acc[i][j][q] = 0.0f;

    for (int k0 = 0; k0 < K; k0 += 16) {
        #pragma unroll
        for (int i = 0; i < 8; i++) As[lk + i][lr] = f2tf(pa[i]);
        {
            uint4 u; u.x=f2tf(pb[0]); u.y=f2tf(pb[1]); u.z=f2tf(pb[2]); u.w=f2tf(pb[3]);
            *(uint4*)&Bs[bk][bc] = u;
            uint4 v; v.x=f2tf(pb[4]); v.y=f2tf(pb[5]); v.z=f2tf(pb[6]); v.w=f2tf(pb[7]);
            *(uint4*)&Bs[bk][bc + 4] = v;
        }
        __syncthreads();

        if (k0 + 16 < K) {
            const float* wp = W + (size_t)(m0 + lr) * K + k0 + 16 + lk;
            float4 a0 = *(const float4*)wp;
            float4 a1 = *(const float4*)(wp + 4);
            pa[0]=a0.x; pa[1]=a0.y; pa[2]=a0.z; pa[3]=a0.w;
            pa[4]=a1.x; pa[5]=a1.y; pa[6]=a1.z; pa[7]=a1.w;
            const float* xp = Xb + (size_t)(k0 + 16 + bk) * NPIX + n0 + bc;
            float4 b0 = *(const float4*)xp;
            float4 b1 = *(const float4*)(xp + 4);
            pb[0]=b0.x; pb[1]=b0.y; pb[2]=b0.z; pb[3]=b0.w;
            pb[4]=b1.x; pb[5]=b1.y; pb[6]=b1.z; pb[7]=b1.w;
        }

        #pragma unroll
        for (int k8 = 0; k8 < 16; k8 += 8) {
            unsigned af[4][4], bf[4][2];
            #pragma unroll
            for (int mf = 0; mf < 4; mf++) {
                int m = wm + mf * 16 + g;
                af[mf][0] = As[k8 + tig][m];
                af[mf][1] = As[k8 + tig][m + 8];
                af[mf][2] = As[k8 + tig + 4][m];
                af[mf][3] = As[k8 + tig + 4][m + 8];
            }
            #pragma unroll
            for (int nf = 0; nf < 4; nf++) {
                int n = wn + nf * 8 + g;
                bf[nf][0] = Bs[k8 + tig][n];
                bf[nf][1] = Bs[k8 + tig + 4][n];
            }
            #pragma unroll
            for (int mf = 0; mf < 4; mf++)
                #pragma unroll
                for (int nf = 0; nf < 4; nf++)
                    mma_tf32(acc[mf][nf], af[mf][0], af[mf][1], af[mf][2], af[mf][3],
                             bf[nf][0], bf[nf][1]);
        }
        __syncthreads();
    }

    #pragma unroll
    for (int mf = 0; mf < 4; mf++) {
        int row = m0 + wm + mf * 16 + g;
        float bv0 = bias[row], bv1 = bias[row + 8];
        #pragma unroll
        for (int nf = 0; nf < 4; nf++) {
            int col = n0 + wn + nf * 8 + tig * 2;
            float2 o0 = make_float2(acc[mf][nf][0] + bv0, acc[mf][nf][1] + bv0);
            float2 o1 = make_float2(acc[mf][nf][2] + bv1, acc[mf][nf][3] + bv1);
            *(float2*)(Yb + (size_t)row * NPIX + col) = o0;
            *(float2*)(Yb + (size_t)(row + 8) * NPIX + col) = o1;
        }
    }
}

// 4) attn[bh][n][m] = (sum_d q[d][n]*k[d][m]) / scale   grid (2,2,256)
__global__ __launch_bounds__(256) void attn_mma(const float* __restrict__ scale)
{
    __shared__ unsigned As[16][136];   // [k=d][n]
    __shared__ unsigned Bs[16][136];   // [k=d][m]

    const int bh = blockIdx.z;
    const float* q   = g_q    + (size_t)bh * 65536;
    const float* kp  = g_k    + (size_t)bh * 65536;
    float*       out = g_attn + (size_t)bh * 65536;

    const int r0 = blockIdx.y * 128;   // n (output rows)
    const int c0 = blockIdx.x * 128;   // m (output cols)

    const int t = threadIdx.x, lane = t & 31, wid = t >> 5;
    const int g = lane >> 2, tig = lane & 3;
    const int wm = (wid >> 2) * 64, wn = (wid & 3) * 32;
    const int kr = t >> 4, kc = (t & 15) * 8;   // both tiles: k-row kr, 8 cols

    float inv = 1.0f / __ldg(scale);

    float pa[8], pb[8];
    {
        const float* qp = q + (size_t)kr * 256 + r0 + kc;
        float4 a0 = *(const float4*)qp; float4 a1 = *(const float4*)(qp + 4);
        pa[0]=a0.x; pa[1]=a0.y; pa[2]=a0.z; pa[3]=a0.w;
        pa[4]=a1.x; pa[5]=a1.y; pa[6]=a1.z; pa[7]=a1.w;
        const float* kpp = kp + (size_t)kr * 256 + c0 + kc;
        float4 b0 = *(const float4*)kpp; float4 b1 = *(const float4*)(kpp + 4);
        pb[0]=b0.x; pb[1]=b0.y; pb[2]=b0.z; pb[3]=b0.w;
        pb[4]=b1.x; pb[5]=b1.y; pb[6]=b1.z; pb[7]=b1.w;
    }

    float acc[4][4][4];
    #pragma unroll
    for (int i = 0; i < 4; i++)
        #pragma unroll
        for (int j = 0; j < 4; j++)
            #pragma unroll
            for (int qq = 0; qq < 4; qq++) acc[i][j][qq] = 0.0f;

    for (int k0 = 0; k0 < 256; k0 += 16) {
        {
            uint4 u; u.x=f2tf(pa[0]); u.y=f2tf(pa[1]); u.z=f2tf(pa[2]); u.w=f2tf(pa[3]);
            *(uint4*)&As[kr][kc] = u;
            uint4 v; v.x=f2tf(pa[4]); v.y=f2tf(pa[5]); v.z=f2tf(pa[6]); v.w=f2tf(pa[7]);
            *(uint4*)&As[kr][kc + 4] = v;
            uint4 w; w.x=f2tf(pb[0]); w.y=f2tf(pb[1]); w.z=f2tf(pb[2]); w.w=f2tf(pb[3]);
            *(uint4*)&Bs[kr][kc] = w;
            uint4 z; z.x=f2tf(pb[4]); z.y=f2tf(pb[5]); z.z=f2tf(pb[6]); z.w=f2tf(pb[7]);
            *(uint4*)&Bs[kr][kc + 4] = z;
        }
        __syncthreads();

        if (k0 + 16 < 256) {
            const float* qp = q + (size_t)(k0 + 16 + kr) * 256 + r0 + kc;
            float4 a0 = *(const float4*)qp; float4 a1 = *(const float4*)(qp + 4);
            pa[0]=a0.x; pa[1]=a0.y; pa[2]=a0.z; pa[3]=a0.w;
            pa[4]=a1.x; pa[5]=a1.y; pa[6]=a1.z; pa[7]=a1.w;
            const float* kpp = kp + (size_t)(k0 + 16 + kr) * 256 + c0 + kc;
            float4 b0 = *(const float4*)kpp; float4 b1 = *(const float4*)(kpp + 4);
            pb[0]=b0.x; pb[1]=b0.y; pb[2]=b0.z; pb[3]=b0.w;
            pb[4]=b1.x; pb[5]=b1.y; pb[6]=b1.z; pb[7]=b1.w;
        }

        #pragma unroll
        for (int k8 = 0; k8 < 16; k8 += 8) {
            unsigned af[4][4], bf[4][2];
            #pragma unroll
            for (int mf = 0; mf < 4; mf++) {
                int m = wm + mf * 16 + g;
                af[mf][0] = As[k8 + tig][m];
                af[mf][1] = As[k8 + tig][m + 8];
                af[mf][2] = As[k8 + tig + 4][m];
                af[mf][3] = As[k8 + tig + 4][m + 8];
            }
            #pragma unroll
            for (int nf = 0; nf < 4; nf++) {
                int n = wn + nf * 8 + g;
                bf[nf][0] = Bs[k8 + tig][n];
                bf[nf][1] = Bs[k8 + tig + 4][n];
            }
            #pragma unroll
            for (int mf = 0; mf < 4; mf++)
                #pragma unroll
                for (int nf = 0; nf < 4; nf++)
                    mma_tf32(acc[mf][nf], af[mf][0], af[mf][1], af[mf][2], af[mf][3],
                             bf[nf][0], bf[nf][1]);
        }
        __syncthreads();
    }

    #pragma unroll
    for (int mf = 0; mf < 4; mf++) {
        int row = r0 + wm + mf * 16 + g;
        #pragma unroll
        for (int nf = 0; nf < 4; nf++) {
            int col = c0 + wn + nf * 8 + tig * 2;
            float2 o0 = make_float2(acc[mf][nf][0] * inv, acc[mf][nf][1] * inv);
            float2 o1 = make_float2(acc[mf][nf][2] * inv, acc[mf][nf][3] * inv);
            *(float2*)(out + (size_t)row * 256 + col) = o0;
            *(float2*)(out + (size_t)(row + 8) * 256 + col) = o1;
        }
    }
}

// 5) sparse mix + softmax
__global__ __launch_bounds__(128) void mix_softmax()
{
    int row = blockIdx.x;
    int t   = threadIdx.x;
    __shared__ float arow[256];
    __shared__ float sp[256];
    __shared__ float red[128];

    const float* src = g_attn + (size_t)row * 256;
    arow[t]       = src[t];
    arow[t + 128] = src[t + 128];
    __syncthreads();

    #pragma unroll
    for (int pp = 0; pp < 2; pp++) {
        int p = t + pp * 128;
        int c = g_csc_cnt[p];
        const int*   ri = g_csc_row + p * 256;
        const float* rv = g_csc_val + p * 256;
        float s = 0.0f;
        for (int j = 0; j < c; j++) s += arow[ri[j]] * rv[j];
        sp[p] = s;
    }
    __syncthreads();

    red[t] = fmaxf(sp[t], sp[t + 128]);
    __syncthreads();
    for (int s = 64; s > 0; s >>= 1) {
        if (t < s) red[t] = fmaxf(red[t], red[t + s]);
        __syncthreads();
    }
    float mx = red[0];
    __syncthreads();

    float e0 = __expf(sp[t] - mx);
    float e1 = __expf(sp[t + 128] - mx);
    red[t] = e0 + e1;
    __syncthreads();
    for (int s = 64; s > 0; s >>= 1) {
        if (t < s) red[t] += red[t + s];
        __syncthreads();
    }
    float inv = 1.0f / red[0];

    float* dst = g_sattn + (size_t)row * 256;
    dst[t]       = e0 * inv;
    dst[t + 128] = e1 * inv;
}

// 6) ao[d][n] = sum_m v[d][m] * sattn[n][m]   grid (2,2,256)
__global__ __launch_bounds__(256) void av_mma()
{
    __shared__ unsigned As[16][136];   // [k=m][d]
    __shared__ unsigned Bs[16][136];   // [k=m][n]

    const int bh = blockIdx.z;
    const float* v  = g_v     + (size_t)bh * 65536;
    const float* sa = g_sattn + (size_t)bh * 65536;
    float*       ao = g_ao    + (size_t)bh * 65536;

    const int r0 = blockIdx.y * 128;   // d (output rows)
    const int c0 = blockIdx.x * 128;   // n (output cols)

    const int t = threadIdx.x, lane = t & 31, wid = t >> 5;
    const int g = lane >> 2, tig = lane & 3;
    const int wm = (wid >> 2) * 64, wn = (wid & 3) * 32;
    const int lr = t >> 1, lk = (t & 1) * 8;

    float pa[8], pb[8];
    {
        const float* vp = v + (size_t)(r0 + lr) * 256 + lk;
        float4 a0 = *(const float4*)vp; float4 a1 = *(const float4*)(vp + 4);
        pa[0]=a0.x; pa[1]=a0.y; pa[2]=a0.z; pa[3]=a0.w;
        pa[4]=a1.x; pa[5]=a1.y; pa[6]=a1.z; pa[7]=a1.w;
        const float* sp = sa + (size_t)(c0 + lr) * 256 + lk;
        float4 b0 = *(const float4*)sp; float4 b1 = *(const float4*)(sp + 4);
        pb[0]=b0.x; pb[1]=b0.y; pb[2]=b0.z; pb[3]=b0.w;
        pb[4]=b1.x; pb[5]=b1.y; pb[6]=b1.z; pb[7]=b1.w;
    }

    float acc[4][4][4];
    #pragma unroll
    for (int i = 0; i < 4; i++)
        #pragma unroll
        for (int j = 0; j < 4; j++)
            #pragma unroll
            for (int qq = 0; qq < 4; qq++) acc[i][j][qq] = 0.0f;

    for (int k0 = 0; k0 < 256; k0 += 16) {
        #pragma unroll
        for (int i = 0; i < 8; i++) {
            As[lk + i][lr] = f2tf(pa[i]);
            Bs[lk + i][lr] = f2tf(pb[i]);
        }
        __syncthreads();

        if (k0 + 16 < 256) {
            const float* vp = v + (size_t)(r0 + lr) * 256 + k0 + 16 + lk;
            float4 a0 = *(const float4*)vp; float4 a1 = *(const float4*)(vp + 4);
            pa[0]=a0.x; pa[1]=a0.y; pa[2]=a0.z; pa[3]=a0.w;
            pa[4]=a1.x; pa[5]=a1.y; pa[6]=a1.z; pa[7]=a1.w;
            const float* sp = sa + (size_t)(c0 + lr) * 256 + k0 + 16 + lk;
            float4 b0 = *(const float4*)sp; float4 b1 = *(const float4*)(sp + 4);
            pb[0]=b0.x; pb[1]=b0.y; pb[2]=b0.z; pb[3]=b0.w;
            pb[4]=b1.x; pb[5]=b1.y; pb[6]=b1.z; pb[7]=b1.w;
        }

        #pragma unroll
        for (int k8 = 0; k8 < 16; k8 += 8) {
            unsigned af[4][4], bf[4][2];
            #pragma unroll
            for (int mf = 0; mf < 4; mf++) {
                int m = wm + mf * 16 + g;
                af[mf][0] = As[k8 + tig][m];
                af[mf][1] = As[k8 + tig][m + 8];
                af[mf][2] = As[k8 + tig + 4][m];
                af[mf][3] = As[k8 + tig + 4][m + 8];
            }
            #pragma unroll
            for (int nf = 0; nf < 4; nf++) {
                int n = wn + nf * 8 + g;
                bf[nf][0] = Bs[k8 + tig][n];
                bf[nf][1] = Bs[k8 + tig + 4][n];
            }
            #pragma unroll
            for (int mf = 0; mf < 4; mf++)
                #pragma unroll
                for (int nf = 0; nf < 4; nf++)
                    mma_tf32(acc[mf][nf], af[mf][0], af[mf][1], af[mf][2], af[mf][3],
                             bf[nf][0], bf[nf][1]);
        }
        __syncthreads();
    }

    #pragma unroll
    for (int mf = 0; mf < 4; mf++) {
        int row = r0 + wm + mf * 16 + g;
        #pragma unroll
        for (int nf = 0; nf < 4; nf++) {
            int col = c0 + wn + nf * 8 + tig * 2;
            float2 o0 = make_float2(acc[mf][nf][0], acc[mf][nf][1]);
            float2 o1 = make_float2(acc[mf][nf][2], acc[mf][nf][3]);
            *(float2*)(ao + (size_t)row * 256 + col) = o0;
            *(float2*)(ao + (size_t)(row + 8) * 256 + col) = o1;
        }
    }
}

// ---------------------------------------------------------------------------
extern "C" void kernel_launch(void* const* d_in, const int* in_sizes, int n_in,
                              void* d_out, int out_size)
{
    const float* x     = (const float*)d_in[0];
    const float* Wq    = (const float*)d_in[1];
    const float* bq    = (const float*)d_in[2];
    const float* Wk    = (const float*)d_in[3];
    const float* bk    = (const float*)d_in[4];
    const float* Wv    = (const float*)d_in[5];
    const float* bv    = (const float*)d_in[6];
    const float* Wo    = (const float*)d_in[7];
    const float* bo    = (const float*)d_in[8];
    const float* coeff = (const float*)d_in[9];
    const float* scale = (const float*)d_in[10];
    float* out = (float*)d_out;

    float *pq, *pk, *pv, *pao;
    cudaGetSymbolAddress((void**)&pq,  g_q);
    cudaGetSymbolAddress((void**)&pk,  g_k);
    cudaGetSymbolAddress((void**)&pv,  g_v);
    cudaGetSymbolAddress((void**)&pao, g_ao);

    sparsify_topk<<<256, 256>>>(coeff);
    build_csc<<<1, 256>>>();

    dim3 gconv(NPIX / 128, COUT / 128, BATCH);          // (2,16,32)
    conv_mma<<<gconv, 256>>>(Wq, bq, x, pq, CIN);
    conv_mma<<<gconv, 256>>>(Wk, bk, x, pk, CIN);
    conv_mma<<<gconv, 256>>>(Wv, bv, x, pv, CIN);

    attn_mma<<<dim3(2, 2, BATCH * HEADS), 256>>>(scale);
    mix_softmax<<<BATCH * HEADS * NPIX, 128>>>();
    av_mma<<<dim3(2, 2, BATCH * HEADS), 256>>>();

    conv_mma<<<gconv, 256>>>(Wo, bo, pao, out, COUT);
}

// round 4
// speedup vs baseline: 2.4912x; 1.2567x over previous
#include <cuda_runtime.h>
#include <cuda_bf16.h>
#include <cstdint>

#define BATCH 32
#define CIN   512
#define COUT  2048
#define HEADS 8
#define DHEAD 256
#define NPIX  256
#define SPARSITY 7

// Scratch: tf32-bit-pattern operands stored as unsigned
__device__ unsigned g_xc [BATCH * CIN * NPIX];    // converted x
__device__ unsigned g_wqc[COUT * CIN];
__device__ unsigned g_wkc[COUT * CIN];
__device__ unsigned g_wvc[COUT * CIN];
__device__ unsigned g_woc[COUT * COUT];

__device__ unsigned g_q    [BATCH * COUT * NPIX];  // tf32 bits
__device__ unsigned g_k    [BATCH * COUT * NPIX];  // tf32 bits
__device__ unsigned g_v    [BATCH * COUT * NPIX];  // tf32 bits
__device__ unsigned g_ao   [BATCH * COUT * NPIX];  // tf32 bits
__device__ float    g_attn [BATCH * HEADS * NPIX * NPIX];  // fp32
__device__ unsigned g_sattn[BATCH * HEADS * NPIX * NPIX];  // tf32 bits

__device__ int   g_t7i[256 * SPARSITY];
__device__ float g_t7v[256 * SPARSITY];
__device__ int   g_csc_row[256 * 256];
__device__ float g_csc_val[256 * 256];
__device__ int   g_csc_cnt[256];

// ---------------------------------------------------------------------------
__device__ __forceinline__ unsigned f2tf(float x) {
    unsigned r;
    asm("cvt.rna.tf32.f32 %0, %1;" : "=r"(r) : "f"(x));
    return r;
}

__device__ __forceinline__ void mma_tf32(float c[4],
    unsigned a0, unsigned a1, unsigned a2, unsigned a3,
    unsigned b0, unsigned b1)
{
    asm volatile(
        "mma.sync.aligned.m16n8k8.row.col.f32.tf32.tf32.f32 "
        "{%0,%1,%2,%3}, {%4,%5,%6,%7}, {%8,%9}, {%0,%1,%2,%3};"
        : "+f"(c[0]), "+f"(c[1]), "+f"(c[2]), "+f"(c[3])
        : "r"(a0), "r"(a1), "r"(a2), "r"(a3), "r"(b0), "r"(b1));
}

__device__ __forceinline__ void cpa16(unsigned saddr, const void* gptr) {
    asm volatile("cp.async.cg.shared.global [%0], [%1], 16;\n"
                 :: "r"(saddr), "l"(gptr));
}
#define CP_COMMIT() asm volatile("cp.async.commit_group;\n")
#define CP_WAIT1()  asm volatile("cp.async.wait_group 1;\n")
#define CP_WAIT0()  asm volatile("cp.async.wait_group 0;\n")

// ---------------------------------------------------------------------------
// 0) elementwise fp32 -> tf32-bits
// ---------------------------------------------------------------------------
__global__ void cvt_tf32(const float4* __restrict__ src, uint4* __restrict__ dst, int n4) {
    int i = blockIdx.x * blockDim.x + threadIdx.x;
    if (i < n4) {
        float4 v = src[i];
        uint4 u;
        u.x = f2tf(v.x); u.y = f2tf(v.y); u.z = f2tf(v.z); u.w = f2tf(v.w);
        dst[i] = u;
    }
}

// ---------------------------------------------------------------------------
// 1) top-7 |coeff| per row
// ---------------------------------------------------------------------------
__global__ void sparsify_topk(const float* __restrict__ coeff) {
    int r = blockIdx.x;
    int t = threadIdx.x;
    __shared__ float av[2048];
    __shared__ float rv[256];
    __shared__ int   ri[256];

    const float* row = coeff + (size_t)r * 2048;
    for (int j = t; j < 2048; j += 256) av[j] = fabsf(row[j]);
    __syncthreads();

    for (int it = 0; it < SPARSITY; it++) {
        float best = -1.0f; int bi = 1 << 30;
        for (int j = t; j < 2048; j += 256) {
            float v = av[j];
            if (v > best) { best = v; bi = j; }
        }
        rv[t] = best; ri[t] = bi;
        __syncthreads();
        for (int s = 128; s > 0; s >>= 1) {
            if (t < s) {
                if (rv[t + s] > rv[t] || (rv[t + s] == rv[t] && ri[t + s] < ri[t])) {
                    rv[t] = rv[t + s]; ri[t] = ri[t + s];
                }
            }
            __syncthreads();
        }
        if (t == 0) {
            int idx = ri[0];
            g_t7i[r * SPARSITY + it] = idx;
            g_t7v[r * SPARSITY + it] = row[idx];
            av[idx] = -2.0f;
        }
        __syncthreads();
    }
}

__global__ void build_csc() {
    int p = threadIdx.x;
    int cnt = 0;
    for (int r = 0; r < 256; r++) {
        #pragma unroll
        for (int j = 0; j < SPARSITY; j++) {
            if (g_t7i[r * SPARSITY + j] == p) {
                g_csc_row[p * 256 + cnt] = r;
                g_csc_val[p * 256 + cnt] = g_t7v[r * SPARSITY + j];
                cnt++;
            }
        }
    }
    g_csc_cnt[p] = cnt;
}

// ---------------------------------------------------------------------------
// GEMM common: 128x128 block, BK=16, 256 thr (8 warps 2x4), warp 64x32,
// mma m16n8k8 tf32, cp.async double-buffered.
// Layouts: row-major tile stride 20 (16 used), k-major tile stride 136.
// ---------------------------------------------------------------------------

// 3) conv1x1: Y[b][o][n] = sum_c W[o][c]*X[b][c][n] + bias[o]   grid (2,16,32)
//    A = W row-major [m][k] (stride-20 tile); B = X k-major [k][n] (stride-136)
__global__ __launch_bounds__(256) void conv_mma2(
    const unsigned* __restrict__ W, const float* __restrict__ bias,
    const unsigned* __restrict__ X, float* __restrict__ Y, int K, int round_out)
{
    __shared__ unsigned As[2][128 * 20];
    __shared__ unsigned Bs[2][16 * 136];

    const int b  = blockIdx.z;
    const int m0 = blockIdx.y * 128;
    const int n0 = blockIdx.x * 128;
    const unsigned* Xb = X + (size_t)b * K * NPIX;
    float*          Yb = Y + (size_t)b * COUT * NPIX;

    const int t = threadIdx.x, lane = t & 31, wid = t >> 5;
    const int g = lane >> 2, tig = lane & 3;
    const int wm = (wid >> 2) * 64, wn = (wid & 3) * 32;

    const unsigned aB = (unsigned)__cvta_generic_to_shared(&As[0][0]);
    const unsigned bB = (unsigned)__cvta_generic_to_shared(&Bs[0][0]);

    // copy ids: A 512 x 16B (row=c>>2, col=(c&3)*4); B 512 x 16B (k=c>>5, col=(c&31)*4)
    const int a_r0 = t >> 1;                 // unused helper; explicit below
    (void)a_r0;

    const int NT = K >> 4;

    // prologue: stage 0
    {
        #pragma unroll
        for (int i = 0; i < 2; i++) {
            int c = t + 256 * i;
            int row = c >> 2, col = (c & 3) * 4;
            cpa16(aB + (unsigned)(row * 20 + col) * 4u,
                  W + (size_t)(m0 + row) * K + col);
        }
        #pragma unroll
        for (int i = 0; i < 2; i++) {
            int c = t + 256 * i;
            int kr = c >> 5, col = (c & 31) * 4;
            cpa16(bB + (unsigned)(kr * 136 + col) * 4u,
                  Xb + (size_t)kr * NPIX + n0 + col);
        }
        CP_COMMIT();
    }

    float acc[4][4][4];
    #pragma unroll
    for (int i = 0; i < 4; i++)
        #pragma unroll
        for (int j = 0; j < 4; j++)
            #pragma unroll
            for (int q = 0; q < 4; q++) acc[i][j][q] = 0.0f;

    for (int it = 0; it < NT; it++) {
        int s = it & 1;
        if (it + 1 < NT) {
            int k0n = (it + 1) << 4, sn = (it + 1) & 1;
            #pragma unroll
            for (int i = 0; i < 2; i++) {
                int c = t + 256 * i;
                int row = c >> 2, col = (c & 3) * 4;
                cpa16(aB + (unsigned)(sn * 128 * 20 + row * 20 + col) * 4u,
                      W + (size_t)(m0 + row) * K + k0n + col);
            }
            #pragma unroll
            for (int i = 0; i < 2; i++) {
                int c = t + 256 * i;
                int kr = c >> 5, col = (c & 31) * 4;
                cpa16(bB + (unsigned)(sn * 16 * 136 + kr * 136 + col) * 4u,
                      Xb + (size_t)(k0n + kr) * NPIX + n0 + col);
            }
            CP_COMMIT();
            CP_WAIT1();
        } else {
            CP_WAIT0();
        }
        __syncthreads();

        const unsigned* A = &As[s][0];
        const unsigned* B = &Bs[s][0];
        #pragma unroll
        for (int k8 = 0; k8 < 16; k8 += 8) {
            unsigned af[4][4], bf[4][2];
            #pragma unroll
            for (int mf = 0; mf < 4; mf++) {
                int m = wm + mf * 16 + g;
                int kk = k8 + tig;
                af[mf][0] = A[m * 20 + kk];
                af[mf][1] = A[(m + 8) * 20 + kk];
                af[mf][2] = A[m * 20 + kk + 4];
                af[mf][3] = A[(m + 8) * 20 + kk + 4];
            }
            #pragma unroll
            for (int nf = 0; nf < 4; nf++) {
                int n = wn + nf * 8 + g;
                bf[nf][0] = B[(k8 + tig) * 136 + n];
                bf[nf][1] = B[(k8 + tig + 4) * 136 + n];
            }
            #pragma unroll
            for (int mf = 0; mf < 4; mf++)
                #pragma unroll
                for (int nf = 0; nf < 4; nf++)
                    mma_tf32(acc[mf][nf], af[mf][0], af[mf][1], af[mf][2], af[mf][3],
                             bf[nf][0], bf[nf][1]);
        }
        __syncthreads();
    }

    #pragma unroll
    for (int mf = 0; mf < 4; mf++) {
        int row = m0 + wm + mf * 16 + g;
        float bv0 = bias[row], bv1 = bias[row + 8];
        #pragma unroll
        for (int nf = 0; nf < 4; nf++) {
            int col = n0 + wn + nf * 8 + tig * 2;
            float v00 = acc[mf][nf][0] + bv0, v01 = acc[mf][nf][1] + bv0;
            float v10 = acc[mf][nf][2] + bv1, v11 = acc[mf][nf][3] + bv1;
            float2 o0, o1;
            if (round_out) {
                o0 = make_float2(__uint_as_float(f2tf(v00)), __uint_as_float(f2tf(v01)));
                o1 = make_float2(__uint_as_float(f2tf(v10)), __uint_as_float(f2tf(v11)));
            } else {
                o0 = make_float2(v00, v01);
                o1 = make_float2(v10, v11);
            }
            *(float2*)(Yb + (size_t)row * NPIX + col) = o0;
            *(float2*)(Yb + (size_t)(row + 8) * NPIX + col) = o1;
        }
    }
}

// 4) attn[bh][n][m] = (sum_d q[d][n]*k[d][m]) / scale   grid (2,2,256)
//    A = q k-major [k][n], B = k k-major [k][m] (both stride-136)
__global__ __launch_bounds__(256) void attn_mma2(const float* __restrict__ scale)
{
    __shared__ unsigned As[2][16 * 136];
    __shared__ unsigned Bs[2][16 * 136];

    const int bh = blockIdx.z;
    const unsigned* q  = g_q + (size_t)bh * 65536;
    const unsigned* kp = g_k + (size_t)bh * 65536;
    float*          out = g_attn + (size_t)bh * 65536;

    const int r0 = blockIdx.y * 128;
    const int c0 = blockIdx.x * 128;

    const int t = threadIdx.x, lane = t & 31, wid = t >> 5;
    const int g = lane >> 2, tig = lane & 3;
    const int wm = (wid >> 2) * 64, wn = (wid & 3) * 32;

    const unsigned aB = (unsigned)__cvta_generic_to_shared(&As[0][0]);
    const unsigned bB = (unsigned)__cvta_generic_to_shared(&Bs[0][0]);

    float inv = 1.0f / __ldg(scale);

    // copies: each tile 16x128 -> 512 x 16B: k=c>>5, col=(c&31)*4
    {
        #pragma unroll
        for (int i = 0; i < 2; i++) {
            int c = t + 256 * i;
            int kr = c >> 5, col = (c & 31) * 4;
            cpa16(aB + (unsigned)(kr * 136 + col) * 4u, q  + (size_t)kr * 256 + r0 + col);
            cpa16(bB + (unsigned)(kr * 136 + col) * 4u, kp + (size_t)kr * 256 + c0 + col);
        }
        CP_COMMIT();
    }

    float acc[4][4][4];
    #pragma unroll
    for (int i = 0; i < 4; i++)
        #pragma unroll
        for (int j = 0; j < 4; j++)
            #pragma unroll
            for (int qq = 0; qq < 4; qq++) acc[i][j][qq] = 0.0f;

    const int NT = 16;  // 256/16
    for (int it = 0; it < NT; it++) {
        int s = it & 1;
        if (it + 1 < NT) {
            int k0n = (it + 1) << 4, sn = (it + 1) & 1;
            #pragma unroll
            for (int i = 0; i < 2; i++) {
                int c = t + 256 * i;
                int kr = c >> 5, col = (c & 31) * 4;
                cpa16(aB + (unsigned)(sn * 16 * 136 + kr * 136 + col) * 4u,
                      q + (size_t)(k0n + kr) * 256 + r0 + col);
                cpa16(bB + (unsigned)(sn * 16 * 136 + kr * 136 + col) * 4u,
                      kp + (size_t)(k0n + kr) * 256 + c0 + col);
            }
            CP_COMMIT();
            CP_WAIT1();
        } else {
            CP_WAIT0();
        }
        __syncthreads();

        const unsigned* A = &As[s][0];
        const unsigned* B = &Bs[s][0];
        #pragma unroll
        for (int k8 = 0; k8 < 16; k8 += 8) {
            unsigned af[4][4], bf[4][2];
            #pragma unroll
            for (int mf = 0; mf < 4; mf++) {
                int m = wm + mf * 16 + g;
                af[mf][0] = A[(k8 + tig) * 136 + m];
                af[mf][1] = A[(k8 + tig) * 136 + m + 8];
                af[mf][2] = A[(k8 + tig + 4) * 136 + m];
                af[mf][3] = A[(k8 + tig + 4) * 136 + m + 8];
            }
            #pragma unroll
            for (int nf = 0; nf < 4; nf++) {
                int n = wn + nf * 8 + g;
                bf[nf][0] = B[(k8 + tig) * 136 + n];
                bf[nf][1] = B[(k8 + tig + 4) * 136 + n];
            }
            #pragma unroll
            for (int mf = 0; mf < 4; mf++)
                #pragma unroll
                for (int nf = 0; nf < 4; nf++)
                    mma_tf32(acc[mf][nf], af[mf][0], af[mf][1], af[mf][2], af[mf][3],
                             bf[nf][0], bf[nf][1]);
        }
        __syncthreads();
    }

    #pragma unroll
    for (int mf = 0; mf < 4; mf++) {
        int row = r0 + wm + mf * 16 + g;
        #pragma unroll
        for (int nf = 0; nf < 4; nf++) {
            int col = c0 + wn + nf * 8 + tig * 2;
            float2 o0 = make_float2(acc[mf][nf][0] * inv, acc[mf][nf][1] * inv);
            float2 o1 = make_float2(acc[mf][nf][2] * inv, acc[mf][nf][3] * inv);
            *(float2*)(out + (size_t)row * 256 + col) = o0;
            *(float2*)(out + (size_t)(row + 8) * 256 + col) = o1;
        }
    }
}

// 5) sparse mix + softmax (writes tf32-rounded probabilities)
__global__ __launch_bounds__(128) void mix_softmax()
{
    int row = blockIdx.x;
    int t   = threadIdx.x;
    __shared__ float arow[256];
    __shared__ float sp[256];
    __shared__ float red[128];

    const float* src = g_attn + (size_t)row * 256;
    arow[t]       = src[t];
    arow[t + 128] = src[t + 128];
    __syncthreads();

    #pragma unroll
    for (int pp = 0; pp < 2; pp++) {
        int p = t + pp * 128;
        int c = g_csc_cnt[p];
        const int*   ri = g_csc_row + p * 256;
        const float* rv = g_csc_val + p * 256;
        float s = 0.0f;
        for (int j = 0; j < c; j++) s += arow[ri[j]] * rv[j];
        sp[p] = s;
    }
    __syncthreads();

    red[t] = fmaxf(sp[t], sp[t + 128]);
    __syncthreads();
    for (int s = 64; s > 0; s >>= 1) {
        if (t < s) red[t] = fmaxf(red[t], red[t + s]);
        __syncthreads();
    }
    float mx = red[0];
    __syncthreads();

    float e0 = __expf(sp[t] - mx);
    float e1 = __expf(sp[t + 128] - mx);
    red[t] = e0 + e1;
    __syncthreads();
    for (int s = 64; s > 0; s >>= 1) {
        if (t < s) red[t] += red[t + s];
        __syncthreads();
    }
    float inv = 1.0f / red[0];

    unsigned* dst = g_sattn + (size_t)row * 256;
    dst[t]       = f2tf(e0 * inv);
    dst[t + 128] = f2tf(e1 * inv);
}

// 6) ao[d][n] = sum_m v[d][m] * sattn[n][m]   grid (2,2,256)
//    A = v row-major [d][k=m]; B = sattn row-major [n][k=m] (both stride-20)
__global__ __launch_bounds__(256) void av_mma2()
{
    __shared__ unsigned As[2][128 * 20];
    __shared__ unsigned Bs[2][128 * 20];

    const int bh = blockIdx.z;
    const unsigned* v  = g_v     + (size_t)bh * 65536;
    const unsigned* sa = g_sattn + (size_t)bh * 65536;
    unsigned*       ao = g_ao    + (size_t)bh * 65536;

    const int r0 = blockIdx.y * 128;   // d
    const int c0 = blockIdx.x * 128;   // n

    const int t = threadIdx.x, lane = t & 31, wid = t >> 5;
    const int g = lane >> 2, tig = lane & 3;
    const int wm = (wid >> 2) * 64, wn = (wid & 3) * 32;

    const unsigned aB = (unsigned)__cvta_generic_to_shared(&As[0][0]);
    const unsigned bB = (unsigned)__cvta_generic_to_shared(&Bs[0][0]);

    {
        #pragma unroll
        for (int i = 0; i < 2; i++) {
            int c = t + 256 * i;
            int row = c >> 2, col = (c & 3) * 4;
            cpa16(aB + (unsigned)(row * 20 + col) * 4u, v  + (size_t)(r0 + row) * 256 + col);
            cpa16(bB + (unsigned)(row * 20 + col) * 4u, sa + (size_t)(c0 + row) * 256 + col);
        }
        CP_COMMIT();
    }

    float acc[4][4][4];
    #pragma unroll
    for (int i = 0; i < 4; i++)
        #pragma unroll
        for (int j = 0; j < 4; j++)
            #pragma unroll
            for (int qq = 0; qq < 4; qq++) acc[i][j][qq] = 0.0f;

    const int NT = 16;
    for (int it = 0; it < NT; it++) {
        int s = it & 1;
        if (it + 1 < NT) {
            int k0n = (it + 1) << 4, sn = (it + 1) & 1;
            #pragma unroll
            for (int i = 0; i < 2; i++) {
                int c = t + 256 * i;
                int row = c >> 2, col = (c & 3) * 4;
                cpa16(aB + (unsigned)(sn * 128 * 20 + row * 20 + col) * 4u,
                      v + (size_t)(r0 + row) * 256 + k0n + col);
                cpa16(bB + (unsigned)(sn * 128 * 20 + row * 20 + col) * 4u,
                      sa + (size_t)(c0 + row) * 256 + k0n + col);
            }
            CP_COMMIT();
            CP_WAIT1();
        } else {
            CP_WAIT0();
        }
        __syncthreads();

        const unsigned* A = &As[s][0];
        const unsigned* B = &Bs[s][0];
        #pragma unroll
        for (int k8 = 0; k8 < 16; k8 += 8) {
            unsigned af[4][4], bf[4][2];
            #pragma unroll
            for (int mf = 0; mf < 4; mf++) {
                int m = wm + mf * 16 + g;
                int kk = k8 + tig;
                af[mf][0] = A[m * 20 + kk];
                af[mf][1] = A[(m + 8) * 20 + kk];
                af[mf][2] = A[m * 20 + kk + 4];
                af[mf][3] = A[(m + 8) * 20 + kk + 4];
            }
            #pragma unroll
            for (int nf = 0; nf < 4; nf++) {
                int n = wn + nf * 8 + g;
                int kk = k8 + tig;
                bf[nf][0] = B[n * 20 + kk];
                bf[nf][1] = B[n * 20 + kk + 4];
            }
            #pragma unroll
            for (int mf = 0; mf < 4; mf++)
                #pragma unroll
                for (int nf = 0; nf < 4; nf++)
                    mma_tf32(acc[mf][nf], af[mf][0], af[mf][1], af[mf][2], af[mf][3],
                             bf[nf][0], bf[nf][1]);
        }
        __syncthreads();
    }

    #pragma unroll
    for (int mf = 0; mf < 4; mf++) {
        int row = r0 + wm + mf * 16 + g;
        #pragma unroll
        for (int nf = 0; nf < 4; nf++) {
            int col = c0 + wn + nf * 8 + tig * 2;
            uint2 o0 = make_uint2(f2tf(acc[mf][nf][0]), f2tf(acc[mf][nf][1]));
            uint2 o1 = make_uint2(f2tf(acc[mf][nf][2]), f2tf(acc[mf][nf][3]));
            *(uint2*)(ao + (size_t)row * 256 + col) = o0;
            *(uint2*)(ao + (size_t)(row + 8) * 256 + col) = o1;
        }
    }
}

// ---------------------------------------------------------------------------
extern "C" void kernel_launch(void* const* d_in, const int* in_sizes, int n_in,
                              void* d_out, int out_size)
{
    const float* x     = (const float*)d_in[0];
    const float* Wq    = (const float*)d_in[1];
    const float* bq    = (const float*)d_in[2];
    const float* Wk    = (const float*)d_in[3];
    const float* bk    = (const float*)d_in[4];
    const float* Wv    = (const float*)d_in[5];
    const float* bv    = (const float*)d_in[6];
    const float* Wo    = (const float*)d_in[7];
    const float* bo    = (const float*)d_in[8];
    const float* coeff = (const float*)d_in[9];
    const float* scale = (const float*)d_in[10];
    float* out = (float*)d_out;

    unsigned *pxc, *pwq, *pwk, *pwv, *pwo, *pq, *pk, *pv, *pao;
    cudaGetSymbolAddress((void**)&pxc, g_xc);
    cudaGetSymbolAddress((void**)&pwq, g_wqc);
    cudaGetSymbolAddress((void**)&pwk, g_wkc);
    cudaGetSymbolAddress((void**)&pwv, g_wvc);
    cudaGetSymbolAddress((void**)&pwo, g_woc);
    cudaGetSymbolAddress((void**)&pq,  g_q);
    cudaGetSymbolAddress((void**)&pk,  g_k);
    cudaGetSymbolAddress((void**)&pv,  g_v);
    cudaGetSymbolAddress((void**)&pao, g_ao);

    // pre-convert external operands to tf32 bits
    {
        int nx = BATCH * CIN * NPIX / 4;
        cvt_tf32<<<(nx + 255) / 256, 256>>>((const float4*)x, (uint4*)pxc, nx);
        int nw = COUT * CIN / 4;
        cvt_tf32<<<(nw + 255) / 256, 256>>>((const float4*)Wq, (uint4*)pwq, nw);
        cvt_tf32<<<(nw + 255) / 256, 256>>>((const float4*)Wk, (uint4*)pwk, nw);
        cvt_tf32<<<(nw + 255) / 256, 256>>>((const float4*)Wv, (uint4*)pwv, nw);
        int no = COUT * COUT / 4;
        cvt_tf32<<<(no + 255) / 256, 256>>>((const float4*)Wo, (uint4*)pwo, no);
    }

    sparsify_topk<<<256, 256>>>(coeff);
    build_csc<<<1, 256>>>();

    dim3 gconv(NPIX / 128, COUT / 128, BATCH);   // (2,16,32)
    conv_mma2<<<gconv, 256>>>(pwq, bq, pxc, (float*)pq, CIN, 1);
    conv_mma2<<<gconv, 256>>>(pwk, bk, pxc, (float*)pk, CIN, 1);
    conv_mma2<<<gconv, 256>>>(pwv, bv, pxc, (float*)pv, CIN, 1);

    attn_mma2<<<dim3(2, 2, BATCH * HEADS), 256>>>(scale);
    mix_softmax<<<BATCH * HEADS * NPIX, 128>>>();
    av_mma2<<<dim3(2, 2, BATCH * HEADS), 256>>>();

    conv_mma2<<<gconv, 256>>>(pwo, bo, pao, out, COUT, 0);
}